// round 13
// baseline (speedup 1.0000x reference)
#include <cuda_runtime.h>

#define NCLS  19
#define DIM   256
#define NPIX  4096
#define NBINS 51
#define NW    (NCLS * DIM)    // 4864 tasks; 1 per warp
#define NBLK  (NW / 4)        // 1216 blocks x 4 warps; 9 blocks/SM

// ---- scratch (no allocations allowed) ----
__device__ int   g_off[NCLS + 1];
__device__ int   g_cnt[NCLS];
__device__ float g_Fs[DIM * NPIX];          // class-sorted values, d-major
__device__ float g_miu[DIM * NCLS];         // [d][c]
__device__ float g_var[DIM * NCLS];
__device__ float g_clsum2[NCLS * 32];       // spread class partial sums
__device__ int   g_ticket;

__device__ __forceinline__ float wredsum(float v) {
#pragma unroll
    for (int m = 16; m; m >>= 1) v += __shfl_xor_sync(0xffffffffu, v, m);
    return v;
}

__device__ __forceinline__ float ex2(float x) {
    float e;
    asm("ex2.approx.ftz.f32 %0, %1;" : "=f"(e) : "f"(x));
    return e;
}

// KDE sub-pass, KB bins from BSTART. Padding-free: full 2-pixel pairs
// (both loads valid, no select), then one predicated single-pixel tail.
template <int KB, int BSTART>
__device__ __forceinline__ void kde_pass(const float* __restrict__ vals, int cnt,
                                         int lane, float a_s, float* sh_out) {
    float acc[KB];
#pragma unroll
    for (int k = 0; k < KB; k++) acc[k] = 0.f;
    int i = lane;
    for (; i + 32 < cnt; i += 64) {
        float fa = vals[i];
        float fb = vals[i + 32];
        float p1a = (-2.f * a_s) * fa, p0a = a_s * fa * fa;
        float p1b = (-2.f * a_s) * fb, p0b = a_s * fb * fb;
#pragma unroll
        for (int k = 0; k < KB; k++) {
            float bk = -5.f + 0.2f * (float)(BSTART + k);
            acc[k] += ex2(fmaf(a_s, bk * bk, fmaf(p1a, bk, p0a)))
                    + ex2(fmaf(a_s, bk * bk, fmaf(p1b, bk, p0b)));
        }
    }
    if (i < cnt) {                        // <=1 divergent tail iteration
        float fa = vals[i];
        float p1a = (-2.f * a_s) * fa, p0a = a_s * fa * fa;
#pragma unroll
        for (int k = 0; k < KB; k++) {
            float bk = -5.f + 0.2f * (float)(BSTART + k);
            acc[k] += ex2(fmaf(a_s, bk * bk, fmaf(p1a, bk, p0a)));
        }
    }
#pragma unroll
    for (int k = 0; k < KB; k++) {
        acc[k] = wredsum(acc[k]);
        if (lane == 0) sh_out[k] = acc[k];
    }
}

// K0: block handles dims d and d+128. Block-local counting sort (labels are
// 16KB, L2-broadcast) + gather into g_Fs + per-(c,d) stats on the L1-hot rows.
__global__ void __launch_bounds__(256) k_gp(const int* __restrict__ lab32,
                                            const float* __restrict__ feature) {
    __shared__ short sperm[NPIX];          // 8KB
    __shared__ int scnt[8][20];            // [warp][class] -> excl prefix
    __shared__ int stot[20];
    __shared__ int soff[20];
    int tid  = threadIdx.x;
    int w    = tid >> 5;
    int lane = tid & 31;

    // words [0,4096): in-bounds under both dtype views of the label buffer.
    int aw[16];
#pragma unroll
    for (int r = 0; r < 16; r++) aw[r] = lab32[tid + r * 256];
    // int64 labels (0..18): all odd words zero; odd words owned by odd tid.
    int any = 0;
    if (tid & 1) {
#pragma unroll
        for (int r = 0; r < 16; r++) any |= aw[r];
    }
    int is32 = __syncthreads_or(any);

    if (lane < 20) scnt[w][lane] = 0;
    __syncwarp();

    int cs[16], rs[16];
#pragma unroll
    for (int r = 0; r < 16; r++) {
        int n = tid + r * 256;
        int c = is32 ? aw[r] : lab32[2 * n];
        c = max(0, min(NCLS - 1, c));
        cs[r] = c;
        unsigned mask = __match_any_sync(0xffffffffu, c);
        int base = scnt[w][c];
        rs[r] = base + __popc(mask & ((1u << lane) - 1u));
        if (lane == (__ffs(mask) - 1)) scnt[w][c] = base + __popc(mask);
        __syncwarp();
    }
    __syncthreads();

    // cross-warp exclusive prefix per class
    if (tid < NCLS) {
        int run = 0;
#pragma unroll
        for (int w2 = 0; w2 < 8; w2++) {
            int t = scnt[w2][tid];
            scnt[w2][tid] = run;
            run += t;
        }
        stot[tid] = run;
    }
    __syncthreads();
    if (tid == 0) {
        int off = 0;
        for (int c = 0; c < NCLS; c++) { soff[c] = off; off += stot[c]; }
    }
    __syncthreads();

#pragma unroll
    for (int r = 0; r < 16; r++) {
        int c = cs[r];
        sperm[soff[c] + scnt[w][c] + rs[r]] = (short)(tid + r * 256);
    }

    if (blockIdx.x == 0) {
        if (tid < NCLS) { g_cnt[tid] = stot[tid]; g_off[tid] = soff[tid]; }
        if (tid == NCLS) g_off[NCLS] = NPIX;
        for (int i = tid; i < NCLS * 32; i += 256) g_clsum2[i] = 0.f;
        if (tid == 255) g_ticket = 0;
    }
    __syncthreads();

#pragma unroll 1
    for (int dd = 0; dd < 2; dd++) {
        int d = blockIdx.x + dd * 128;
        const float* __restrict__ src = feature + d * NPIX;
        float* __restrict__ dst = g_Fs + d * NPIX;
        for (int j = tid; j < NPIX; j += 256)
            dst[j] = src[sperm[j]];
        __syncthreads();
        // stats: warp w reduces classes w, w+8, w+16 from the L1-hot row
        for (int c = w; c < NCLS; c += 8) {
            int off = soff[c];
            int cnt = stot[c];
            float s1 = 0.f, s2 = 0.f;
            for (int i = lane; i < cnt; i += 32) {
                float f = dst[off + i];
                s1 += f;
                s2 = fmaf(f, f, s2);
            }
            s1 = wredsum(s1);
            s2 = wredsum(s2);
            if (lane == 0 && cnt > 0) {
                float cm  = (float)cnt;
                float miu = s1 / cm;
                g_miu[d * NCLS + c] = miu;
                g_var[d * NCLS + c] = fmaxf(s2 / cm - miu * miu, 1e-12f);
            }
        }
        __syncthreads();
    }
}

// K1: pure KDE + epilogue. One warp per (c,d), contiguous reads, static grid.
__global__ void __launch_bounds__(128, 9)
k_main(const float* __restrict__ feature, float* __restrict__ out, int nf) {
    __shared__ float sh[4][52];
    int wslot = threadIdx.x >> 5;
    int wtask = blockIdx.x * 4 + wslot;   // 0..4863
    int lane = threadIdx.x & 31;
    int c = wtask >> 8;
    int d = wtask & 255;
    int off = g_off[c];
    int cnt = g_off[c + 1] - off;
    const float LOG2E = 1.4426950408889634f;

    if (cnt > 0) {
        const float* __restrict__ fp = g_Fs + d * NPIX + off;
        float miu = g_miu[d * NCLS + c];
        float var = g_var[d * NCLS + c];

        // vs = var/25 ; base-2 coef: -12.5*log2e/var
        float a_s = -12.5f * LOG2E / var;

        kde_pass<26, 0>(fp, cnt, lane, a_s, &sh[wslot][0]);
        kde_pass<25, 26>(fp, cnt, lane, a_s, &sh[wslot][26]);
        __syncwarp();

        // epilogue: lane k owns bins k and k+32
        bool hi = lane < (NBINS - 32);
        float sv0 = sh[wslot][lane];
        float sv1 = hi ? sh[wslot][lane + 32] : 0.f;
        float sumS = wredsum(sv0 + sv1);

        float at = -0.5f * LOG2E / var;
        float b0 = fmaf(0.2f, (float)lane, -5.f);
        float b1 = b0 + 6.4f;
        float d0 = b0 - miu, d1 = b1 - miu;
        float g0 = ex2(at * d0 * d0);
        float g1 = hi ? ex2(at * d1 * d1) : 0.f;
        float sumT = wredsum(g0 + g1);

        float invS = 1.f / fmaxf(sumS, 1e-30f);
        float invT = 1.f / fmaxf(sumT, 1e-30f);

        float df0 = sv0 * invS - g0 * invT;
        float df1 = sv1 * invS - g1 * invT;
        float ad0 = fabsf(df0), ad1 = fabsf(df1);
        float l0 = (ad0 < 1.f) ? 0.5f * df0 * df0 : ad0 - 0.5f;
        float l1 = (ad1 < 1.f) ? 0.5f * df1 * df1 : ad1 - 0.5f;
        if (!hi) l1 = 0.f;

        float sl = wredsum(l0 + l1);
        if (lane == 0) atomicAdd(&g_clsum2[c * 32 + (d & 31)], sl);
    }

    // publish, ticket; the last of the NW warps finalizes.
    __threadfence();
    int tk = 0;
    if (lane == 0) tk = atomicAdd(&g_ticket, 1);
    tk = __shfl_sync(0xffffffffu, tk, 0);
    if (tk == NW - 1) {
        float v = 0.f, a = 0.f;
#pragma unroll
        for (int j = 1; j < NCLS; j++) {          // class 0 excluded
            int cj = __ldcg(&g_cnt[j]);
            float x = __ldcg(&g_clsum2[j * 32 + lane]);
            if (cj > 0) { v += x; a += (lane == 0) ? 1.f : 0.f; }
        }
        v = wredsum(v);
        a = wredsum(a);
        if (lane == 0) out[0] = (v * (1.f / 13056.f)) / (a + 1e-12f);
    }

    // output copy: out[1..nf] = feature[0..nf), overlapped across blocks
    int gt = blockIdx.x * 128 + threadIdx.x;
    for (int j = gt; j < nf; j += NBLK * 128)
        out[1 + j] = feature[j];
}

extern "C" void kernel_launch(void* const* d_in, const int* in_sizes, int n_in,
                              void* d_out, int out_size) {
    // Inputs: feature (1048576 f32) and label (4096 px); smaller buffer = label.
    int fi = 0, li = 1;
    if (n_in >= 2 && in_sizes[0] < in_sizes[1]) { fi = 1; li = 0; }
    const float* feature = (const float*)d_in[fi];
    const int*   label   = (const int*)d_in[li];
    float* out = (float*)d_out;

    int nf = out_size - 1;
    int cap = DIM * NPIX;
    if (nf > cap) nf = cap;
    if (nf < 0) nf = 0;

    k_gp<<<128, 256>>>(label, feature);
    k_main<<<NBLK, 128>>>(feature, out, nf);
}

// round 15
// speedup vs baseline: 1.0678x; 1.0678x over previous
#include <cuda_runtime.h>

#define NCLS  19
#define DIM   256
#define NPIX  4096
#define NBINS 51
#define NW    (NCLS * DIM)    // 4864 tasks; 1 per warp
#define NBLK  (NW / 4)        // 1216 blocks x 4 warps; 9 blocks/SM

// ---- scratch (no allocations allowed) ----
__device__ int   g_off[NCLS + 1];
__device__ int   g_cnt[NCLS];
__device__ float g_Fs[DIM * NPIX];          // class-sorted values, d-major
__device__ float g_clsum2[NCLS * 32];       // spread class partial sums
__device__ int   g_ticket;

__device__ __forceinline__ float wredsum(float v) {
#pragma unroll
    for (int m = 16; m; m >>= 1) v += __shfl_xor_sync(0xffffffffu, v, m);
    return v;
}

__device__ __forceinline__ float ex2(float x) {
    float e;
    asm("ex2.approx.ftz.f32 %0, %1;" : "=f"(e) : "f"(x));
    return e;
}

// Recurrence KDE: e_{k+1} = e_k * t_k, t_{k+1} = t_k * sigma. Re-anchored via
// direct EX2 every SEG bins; chain biased by 2^88 (unscaled at reduction) so
// FTZ underflow only hits bins whose true value is < ~2^-20 of relevance.
// Valid for var >= 0.6 (|a_s| <= ~30); caller guards.
template <int KB, int BSTART>
__device__ __forceinline__ void kde_rec(const float* __restrict__ vals, int cnt,
                                        int lane, float a_s, float sg,
                                        float* sh_out) {
    constexpr int SEG = KB / 3;           // 24 -> 8, 27 -> 9
    float acc[KB];
#pragma unroll
    for (int k = 0; k < KB; k++) acc[k] = 0.f;
    float as04  = 0.4f  * a_s;
    float as004 = 0.04f * a_s;
    int i = lane;
    for (; i + 32 < cnt; i += 64) {
        float fa = vals[i];
        float fb = vals[i + 32];
#pragma unroll
        for (int s = 0; s < 3; s++) {
            const int s0 = s * SEG;
            const int L  = (s == 2) ? (KB - 2 * SEG) : SEG;
            float bk = -5.f + 0.2f * (float)(BSTART + s0);
            float da = bk - fa, db = bk - fb;
            float Ea = ex2(fmaf(a_s * da, da, 88.f));           // biased anchor
            float Eb = ex2(fmaf(a_s * db, db, 88.f));
            float ta = ex2(fminf(fmaf(as04, da, as004), 126.f)); // clamp: no inf
            float tb = ex2(fminf(fmaf(as04, db, as004), 126.f));
#pragma unroll
            for (int j = 0; j < L; j++) {
                acc[s0 + j] += Ea + Eb;
                Ea *= ta; Eb *= tb;
                ta *= sg; tb *= sg;
            }
        }
    }
    if (i < cnt) {                        // <=1 single-pixel tail (biased too)
        float fa = vals[i];
        float p1 = (-2.f * a_s) * fa;
        float p0 = fmaf(a_s * fa, fa, 88.f);
#pragma unroll
        for (int k = 0; k < KB; k++) {
            float bk = -5.f + 0.2f * (float)(BSTART + k);
            acc[k] += ex2(fmaf(a_s, bk * bk, fmaf(p1, bk, p0)));
        }
    }
#pragma unroll
    for (int k = 0; k < KB; k++) {
        acc[k] = wredsum(acc[k]) * 3.2311742677852644e-27f;   // * 2^-88
        if (lane == 0) sh_out[k] = acc[k];
    }
}

// Direct per-bin EX2 path (fallback for small var; always correct).
template <int KB, int BSTART>
__device__ __noinline__ void kde_direct(const float* __restrict__ vals, int cnt,
                                        int lane, float a_s, float* sh_out) {
    float acc[KB];
#pragma unroll
    for (int k = 0; k < KB; k++) acc[k] = 0.f;
    for (int i = lane; i < cnt; i += 32) {
        float fa = vals[i];
        float p1 = (-2.f * a_s) * fa, p0 = a_s * fa * fa;
#pragma unroll
        for (int k = 0; k < KB; k++) {
            float bk = -5.f + 0.2f * (float)(BSTART + k);
            acc[k] += ex2(fmaf(a_s, bk * bk, fmaf(p1, bk, p0)));
        }
    }
#pragma unroll
    for (int k = 0; k < KB; k++) {
        acc[k] = wredsum(acc[k]);
        if (lane == 0) sh_out[k] = acc[k];
    }
}

// K0: block handles dims d and d+128. Block-local counting sort (labels are
// 16KB, L2-broadcast) + gather into g_Fs. Minimal (R12 configuration).
__global__ void __launch_bounds__(256) k_gp(const int* __restrict__ lab32,
                                            const float* __restrict__ feature) {
    __shared__ short sperm[NPIX];          // 8KB
    __shared__ int scnt[8][20];            // [warp][class] -> excl prefix
    __shared__ int stot[20];
    __shared__ int soff[20];
    int tid  = threadIdx.x;
    int w    = tid >> 5;
    int lane = tid & 31;

    // words [0,4096): in-bounds under both dtype views of the label buffer.
    int aw[16];
#pragma unroll
    for (int r = 0; r < 16; r++) aw[r] = lab32[tid + r * 256];
    // int64 labels (0..18): all odd words zero; odd words owned by odd tid.
    int any = 0;
    if (tid & 1) {
#pragma unroll
        for (int r = 0; r < 16; r++) any |= aw[r];
    }
    int is32 = __syncthreads_or(any);

    if (lane < 20) scnt[w][lane] = 0;
    __syncwarp();

    int cs[16], rs[16];
#pragma unroll
    for (int r = 0; r < 16; r++) {
        int n = tid + r * 256;
        int c = is32 ? aw[r] : lab32[2 * n];
        c = max(0, min(NCLS - 1, c));
        cs[r] = c;
        unsigned mask = __match_any_sync(0xffffffffu, c);
        int base = scnt[w][c];
        rs[r] = base + __popc(mask & ((1u << lane) - 1u));
        if (lane == (__ffs(mask) - 1)) scnt[w][c] = base + __popc(mask);
        __syncwarp();
    }
    __syncthreads();

    // cross-warp exclusive prefix per class
    if (tid < NCLS) {
        int run = 0;
#pragma unroll
        for (int w2 = 0; w2 < 8; w2++) {
            int t = scnt[w2][tid];
            scnt[w2][tid] = run;
            run += t;
        }
        stot[tid] = run;
    }
    __syncthreads();
    if (tid == 0) {
        int off = 0;
        for (int c = 0; c < NCLS; c++) { soff[c] = off; off += stot[c]; }
    }
    __syncthreads();

#pragma unroll
    for (int r = 0; r < 16; r++) {
        int c = cs[r];
        sperm[soff[c] + scnt[w][c] + rs[r]] = (short)(tid + r * 256);
    }

    if (blockIdx.x == 0) {
        if (tid < NCLS) { g_cnt[tid] = stot[tid]; g_off[tid] = soff[tid]; }
        if (tid == NCLS) g_off[NCLS] = NPIX;
        for (int i = tid; i < NCLS * 32; i += 256) g_clsum2[i] = 0.f;
        if (tid == 255) g_ticket = 0;
    }
    __syncthreads();

#pragma unroll 1
    for (int dd = 0; dd < 2; dd++) {
        int d = blockIdx.x + dd * 128;
        const float* __restrict__ src = feature + d * NPIX;
        float* __restrict__ dst = g_Fs + d * NPIX;
        for (int j = tid; j < NPIX; j += 256)
            dst[j] = src[sperm[j]];
    }
}

// K1: one warp per (c,d). Stats pass (warms L1) + recurrence KDE (24+27 bin
// sub-passes) + epilogue + spread atomic + ticketed finalize + copy.
__global__ void __launch_bounds__(128, 9)
k_main(const float* __restrict__ feature, float* __restrict__ out, int nf) {
    __shared__ float sh[4][52];
    int wslot = threadIdx.x >> 5;
    int wtask = blockIdx.x * 4 + wslot;   // 0..4863
    int lane = threadIdx.x & 31;
    int c = wtask >> 8;
    int d = wtask & 255;
    int off = g_off[c];
    int cnt = g_off[c + 1] - off;
    const float LOG2E = 1.4426950408889634f;

    if (cnt > 0) {
        const float* __restrict__ fp = g_Fs + d * NPIX + off;

        // pass 1: mean/var (also warms L1 for the KDE passes)
        float s1 = 0.f, s2 = 0.f;
        for (int i = lane; i < cnt; i += 32) {
            float f = fp[i];
            s1 += f;
            s2 = fmaf(f, f, s2);
        }
        s1 = wredsum(s1);
        s2 = wredsum(s2);
        float cm  = (float)cnt;
        float miu = s1 / cm;
        float var = fmaxf(s2 / cm - miu * miu, 1e-12f);

        // vs = var/25 ; base-2 coef: -12.5*log2e/var
        float a_s = -12.5f * LOG2E / var;

        if (var >= 0.6f) {
            float sg = ex2(0.08f * a_s);      // per-task recurrence ratio
            kde_rec<24, 0>(fp, cnt, lane, a_s, sg, &sh[wslot][0]);
            kde_rec<27, 24>(fp, cnt, lane, a_s, sg, &sh[wslot][24]);
        } else {
            kde_direct<24, 0>(fp, cnt, lane, a_s, &sh[wslot][0]);
            kde_direct<27, 24>(fp, cnt, lane, a_s, &sh[wslot][24]);
        }
        __syncwarp();

        // epilogue: lane k owns bins k and k+32
        bool hi = lane < (NBINS - 32);
        float sv0 = sh[wslot][lane];
        float sv1 = hi ? sh[wslot][lane + 32] : 0.f;
        float sumS = wredsum(sv0 + sv1);

        float at = -0.5f * LOG2E / var;
        float b0 = fmaf(0.2f, (float)lane, -5.f);
        float b1 = b0 + 6.4f;
        float d0 = b0 - miu, d1 = b1 - miu;
        float g0 = ex2(at * d0 * d0);
        float g1 = hi ? ex2(at * d1 * d1) : 0.f;
        float sumT = wredsum(g0 + g1);

        float invS = 1.f / fmaxf(sumS, 1e-30f);
        float invT = 1.f / fmaxf(sumT, 1e-30f);

        float df0 = sv0 * invS - g0 * invT;
        float df1 = sv1 * invS - g1 * invT;
        float ad0 = fabsf(df0), ad1 = fabsf(df1);
        float l0 = (ad0 < 1.f) ? 0.5f * df0 * df0 : ad0 - 0.5f;
        float l1 = (ad1 < 1.f) ? 0.5f * df1 * df1 : ad1 - 0.5f;
        if (!hi) l1 = 0.f;

        float sl = wredsum(l0 + l1);
        if (lane == 0) atomicAdd(&g_clsum2[c * 32 + (d & 31)], sl);
    }

    // publish, ticket; the last of the NW warps finalizes.
    __threadfence();
    int tk = 0;
    if (lane == 0) tk = atomicAdd(&g_ticket, 1);
    tk = __shfl_sync(0xffffffffu, tk, 0);
    if (tk == NW - 1) {
        float v = 0.f, a = 0.f;
#pragma unroll
        for (int j = 1; j < NCLS; j++) {          // class 0 excluded
            int cj = __ldcg(&g_cnt[j]);
            float x = __ldcg(&g_clsum2[j * 32 + lane]);
            if (cj > 0) { v += x; a += (lane == 0) ? 1.f : 0.f; }
        }
        v = wredsum(v);
        a = wredsum(a);
        if (lane == 0) out[0] = (v * (1.f / 13056.f)) / (a + 1e-12f);
    }

    // output copy: out[1..nf] = feature[0..nf), overlapped across blocks
    int gt = blockIdx.x * 128 + threadIdx.x;
    for (int j = gt; j < nf; j += NBLK * 128)
        out[1 + j] = feature[j];
}

extern "C" void kernel_launch(void* const* d_in, const int* in_sizes, int n_in,
                              void* d_out, int out_size) {
    // Inputs: feature (1048576 f32) and label (4096 px); smaller buffer = label.
    int fi = 0, li = 1;
    if (n_in >= 2 && in_sizes[0] < in_sizes[1]) { fi = 1; li = 0; }
    const float* feature = (const float*)d_in[fi];
    const int*   label   = (const int*)d_in[li];
    float* out = (float*)d_out;

    int nf = out_size - 1;
    int cap = DIM * NPIX;
    if (nf > cap) nf = cap;
    if (nf < 0) nf = 0;

    k_gp<<<128, 256>>>(label, feature);
    k_main<<<NBLK, 128>>>(feature, out, nf);
}